// round 12
// baseline (speedup 1.0000x reference)
#include <cuda_runtime.h>
#include <cstdint>
#include <cfloat>

#define BB 8
#define NN 8192
#define SS 1024
#define KK 32
#define CC 64
#define DD 128
#define EPSF 1e-5f

// output layout: new_xyz (8,1024,3), feature (8,128,1024), new_xyz, feature
#define OFF_F1  24576
#define OFF_NX2 1073152
#define OFF_F2  1097728

// mega-kernel block ranges
#define FPS_BLKS   BB
#define FEATZ_BLKS (BB*NN/512)          // 128
#define KNN_BLKS   (BB*NN/512)          // 128

// ---------------- scratch (device globals; no allocation) ----------------
__device__ float g_f[BB*NN*CC];                 // 16 MB: per-point features
__device__ float g_z[(size_t)BB*NN*DD];         // 32 MB: z[n][o] = f[n]·W1col(o)
__device__ int   g_fps[BB*SS];
__device__ int   g_knn[(size_t)BB*NN*KK];       // 8 MB: top-32 for ALL points
__device__ float g_u[BB*SS*DD];                 // per-query layer-1 bias term
// prepped (bn-folded) weights
__device__ float g_c1s[CC*3], g_t1[CC];
__device__ float g_c2s[CC*CC], g_t2c[CC];
__device__ float g_W1s[CC*DD];   // [d][o] = lconv1_w[o][d]      * s1l[o]
__device__ float g_Wd [CC*DD];   // [d][o] = (W[o][64+d]-W[o][d])* s1l[o]
__device__ float g_t1l[DD];
__device__ float g_W2s[DD*DD];   // [e][o] = lconv2_w[o][e] * s2l[o]
__device__ float g_t2l[DD];

// ---------------- packed f32x2 helpers (per-lane rn == scalar rn) ----------------
__device__ __forceinline__ unsigned long long pk2(float a, float b) {
    unsigned long long r; asm("mov.b64 %0, {%1,%2};" : "=l"(r) : "f"(a), "f"(b)); return r;
}
__device__ __forceinline__ void upk2(unsigned long long v, float& a, float& b) {
    asm("mov.b64 {%0,%1}, %2;" : "=f"(a), "=f"(b) : "l"(v));
}
__device__ __forceinline__ unsigned long long add2(unsigned long long a, unsigned long long b) {
    unsigned long long r; asm("add.rn.f32x2 %0, %1, %2;" : "=l"(r) : "l"(a), "l"(b)); return r;
}
__device__ __forceinline__ unsigned long long mul2(unsigned long long a, unsigned long long b) {
    unsigned long long r; asm("mul.rn.f32x2 %0, %1, %2;" : "=l"(r) : "l"(a), "l"(b)); return r;
}

// ---------------- prep: fold BN into weights ----------------
__global__ void prep_kernel(
    const float* __restrict__ c1w, const float* __restrict__ c2w,
    const float* __restrict__ l1w, const float* __restrict__ l2w,
    const float* __restrict__ b1g, const float* __restrict__ b1b, const float* __restrict__ b1m, const float* __restrict__ b1v,
    const float* __restrict__ b2g, const float* __restrict__ b2b, const float* __restrict__ b2m, const float* __restrict__ b2v,
    const float* __restrict__ g1g, const float* __restrict__ g1b, const float* __restrict__ g1m, const float* __restrict__ g1v,
    const float* __restrict__ g2g, const float* __restrict__ g2b, const float* __restrict__ g2m, const float* __restrict__ g2v)
{
    int t = blockIdx.x * blockDim.x + threadIdx.x;
    int st = gridDim.x * blockDim.x;
    for (int i = t; i < CC*3; i += st) { int e = i/3; float s = b1g[e]*rsqrtf(b1v[e]+EPSF); g_c1s[i] = c1w[i]*s; }
    for (int e = t; e < CC; e += st)  { float s = b1g[e]*rsqrtf(b1v[e]+EPSF); g_t1[e] = b1b[e]-b1m[e]*s; }
    for (int i = t; i < CC*CC; i += st){ int f = i/CC; float s = b2g[f]*rsqrtf(b2v[f]+EPSF); g_c2s[i] = c2w[i]*s; }
    for (int f = t; f < CC; f += st)  { float s = b2g[f]*rsqrtf(b2v[f]+EPSF); g_t2c[f] = b2b[f]-b2m[f]*s; }
    for (int i = t; i < CC*DD; i += st){
        int d = i / DD, o = i % DD;
        float s = g1g[o]*rsqrtf(g1v[o]+EPSF);
        g_W1s[i] = l1w[o*DD + d]*s;
        g_Wd [i] = (l1w[o*DD + CC + d] - l1w[o*DD + d])*s;
    }
    for (int o = t; o < DD; o += st) { float s = g1g[o]*rsqrtf(g1v[o]+EPSF); g_t1l[o] = g1b[o]-g1m[o]*s; }
    for (int i = t; i < DD*DD; i += st){
        int e = i / DD, o = i % DD;
        float s = g2g[o]*rsqrtf(g2v[o]+EPSF);
        g_W2s[i] = l2w[o*DD + e]*s;
    }
    for (int o = t; o < DD; o += st) { float s = g2g[o]*rsqrtf(g2v[o]+EPSF); g_t2l[o] = g2b[o]-g2m[o]*s; }
}

// ---------------- K1: MEGA — fps (0..7) + feat+z (8..135) + full-knn (136..263) ----------------
__global__ void __launch_bounds__(512) mega_kernel(const float* __restrict__ x, float* __restrict__ out)
{
    int tid = threadIdx.x;
    if (blockIdx.x < FPS_BLKS) {
        // ---------------- FPS path (unchanged from R11) ----------------
        __shared__ unsigned int pd[2][16];
        __shared__ unsigned int pi[2][16];
        int b = blockIdx.x;
        int lane = tid & 31, wid = tid >> 5;
        const float* xb = x + (size_t)b * NN * 3;

        float rd[16];
        unsigned long long rx2[8], ry2[8], rz2[8];
#pragma unroll
        for (int jp = 0; jp < 8; jp++) {
            int i0 = tid + (2*jp)*512, i1 = i0 + 512;
            float ax = xb[i0*3], ay = xb[i0*3+1], az = xb[i0*3+2];
            float bx_ = xb[i1*3], by_ = xb[i1*3+1], bz_ = xb[i1*3+2];
            rx2[jp] = pk2(ax, bx_); ry2[jp] = pk2(ay, by_); rz2[jp] = pk2(az, bz_);
            rd[2*jp] = 1e10f; rd[2*jp+1] = 1e10f;
        }
        float cx = __ldg(xb), cy = __ldg(xb+1), cz = __ldg(xb+2);
        int far = 0;

        for (int t = 0; t < SS; t++) {
            if (tid == 0) {
                g_fps[b*SS + t] = far;
                int o1 = (b*SS + t) * 3;
                out[o1] = cx; out[o1+1] = cy; out[o1+2] = cz;
                out[OFF_NX2+o1] = cx; out[OFF_NX2+o1+1] = cy; out[OFF_NX2+o1+2] = cz;
            }
            unsigned long long nx = pk2(-cx, -cx), ny = pk2(-cy, -cy), nz = pk2(-cz, -cz);
#pragma unroll
            for (int jp = 0; jp < 8; jp++) {
                unsigned long long dx = add2(rx2[jp], nx);
                unsigned long long dy = add2(ry2[jp], ny);
                unsigned long long dz = add2(rz2[jp], nz);
                unsigned long long s  = add2(add2(mul2(dx,dx), mul2(dy,dy)), mul2(dz,dz));
                float s0, s1; upk2(s, s0, s1);
                rd[2*jp]   = fminf(rd[2*jp],   s0);
                rd[2*jp+1] = fminf(rd[2*jp+1], s1);
            }
            float m = rd[0];
#pragma unroll
            for (int j = 1; j < 16; j++) m = fmaxf(m, rd[j]);
            int j0 = 15;
#pragma unroll
            for (int j = 14; j >= 0; j--) if (rd[j] == m) j0 = j;
            unsigned int mb  = __float_as_uint(m);
            unsigned int inv = (unsigned)(NN-1 - (tid + j0*512));
            unsigned int wmax = __reduce_max_sync(0xffffffffu, mb);
            unsigned int winv = __reduce_max_sync(0xffffffffu, (mb == wmax) ? inv : 0u);
            if (lane == 0) { pd[t & 1][wid] = wmax; pi[t & 1][wid] = winv; }
            __syncthreads();
            unsigned int d2 = pd[t & 1][lane & 15];
            unsigned int i2 = pi[t & 1][lane & 15];
            unsigned int gmax = __reduce_max_sync(0xffffffffu, d2);
            unsigned int ginv = __reduce_max_sync(0xffffffffu, (d2 == gmax) ? i2 : 0u);
            far = NN-1 - (int)ginv;
            cx = __ldg(xb + far*3); cy = __ldg(xb + far*3 + 1); cz = __ldg(xb + far*3 + 2);
        }
    } else if (blockIdx.x < FPS_BLKS + FEATZ_BLKS) {
        // ---------------- feat + z path ----------------
        __shared__ float sc1[CC*3], st1[CC], st2[CC];
        __shared__ float4 sc2[CC*16];       // 16 KB
        __shared__ float  sW1t[DD*CC];      // 32 KB, [o][d] transposed for broadcast reads
        for (int i = tid; i < CC*3; i += 512) sc1[i] = g_c1s[i];
        for (int i = tid; i < CC; i += 512) { st1[i] = g_t1[i]; st2[i] = g_t2c[i]; }
        for (int i = tid; i < CC*16; i += 512) sc2[i] = ((const float4*)g_c2s)[i];
        for (int i = tid; i < DD*CC; i += 512) {
            int o = i >> 6, d = i & 63;
            sW1t[i] = g_W1s[d*DD + o];
        }
        __syncthreads();

        int p = (blockIdx.x - FPS_BLKS) * 512 + tid;      // 0..65535
        float x0 = x[p*3], x1 = x[p*3+1], x2 = x[p*3+2];
        float h[CC];
#pragma unroll
        for (int e = 0; e < CC; e++)
            h[e] = fmaxf(fmaf(x2, sc1[e*3+2], fmaf(x1, sc1[e*3+1], x0*sc1[e*3])) + st1[e], 0.f);

        float f[CC];
        float* outf = g_f + (size_t)p * CC;
        for (int o = 0; o < CC; o++) {
            float a0=0.f, a1=0.f, a2=0.f, a3=0.f;
#pragma unroll
            for (int e4 = 0; e4 < 16; e4++) {
                float4 w = sc2[o*16 + e4];
                a0 = fmaf(h[e4*4+0], w.x, a0);
                a1 = fmaf(h[e4*4+1], w.y, a1);
                a2 = fmaf(h[e4*4+2], w.z, a2);
                a3 = fmaf(h[e4*4+3], w.w, a3);
            }
            float v = fmaxf((a0+a1)+(a2+a3) + st2[o], 0.f);
            f[o] = v;
            outf[o] = v;
        }

        // z[p][o] = f·W1col(o): same pairing & accumulator split as old l1 loop
        float4* zrow = (float4*)(g_z + (size_t)p * DD);
        for (int o4 = 0; o4 < DD/4; o4++) {
            float zz[4];
#pragma unroll
            for (int u2 = 0; u2 < 4; u2++) {
                int o = o4*4 + u2;
                const float4* w4 = (const float4*)(sW1t + o*CC);
                float a0=0.f, a1=0.f, a2=0.f, a3=0.f;
#pragma unroll
                for (int d4 = 0; d4 < 16; d4++) {
                    float4 w = w4[d4];
                    a0 = fmaf(f[d4*4+0], w.x, a0);
                    a1 = fmaf(f[d4*4+1], w.y, a1);
                    a2 = fmaf(f[d4*4+2], w.z, a2);
                    a3 = fmaf(f[d4*4+3], w.w, a3);
                }
                zz[u2] = (a0+a1)+(a2+a3);
            }
            float4 v4; v4.x = zz[0]; v4.y = zz[1]; v4.z = zz[2]; v4.w = zz[3];
            zrow[o4] = v4;
        }
    } else {
        // ---------------- full-KNN path: thread per query, ALL points are queries ----------------
        __shared__ float px[2048], py[2048], pz[2048];
        int g = (blockIdx.x - FPS_BLKS - FEATZ_BLKS) * 512 + tid;   // 0..65535
        int b = g >> 13, n = g & (NN-1);
        const float* xb = x + (size_t)b * NN * 3;
        float qx = xb[n*3], qy = xb[n*3+1], qz = xb[n*3+2];

        float bd[KK]; int bi[KK];
#pragma unroll
        for (int j = 0; j < KK; j++) { bd[j] = 3.4e38f; bi[j] = 0; }
        float worst = 3.4e38f;

        for (int base = 0; base < NN; base += 2048) {
            __syncthreads();
            for (int i = tid; i < 2048; i += 512) {
                int nn = base + i;
                px[i] = xb[nn*3]; py[i] = xb[nn*3+1]; pz[i] = xb[nn*3+2];
            }
            __syncthreads();
#pragma unroll 4
            for (int i = 0; i < 2048; i++) {
                float dx = qx-px[i], dy = qy-py[i], dz = qz-pz[i];
                float d = fmaf(dz, dz, fmaf(dy, dy, dx*dx));
                if (d < worst) {
                    int j = KK - 1;
                    while (j > 0 && bd[j-1] > d) { bd[j] = bd[j-1]; bi[j] = bi[j-1]; j--; }
                    bd[j] = d; bi[j] = base + i;
                    worst = bd[KK-1];
                }
            }
        }
        int* kn = g_knn + (size_t)g * KK;
#pragma unroll
        for (int j = 0; j < KK; j++) kn[j] = bi[j];
    }
}

// ---------------- K2: u[s][o] = c·(Wb-Wa)'[o] + t1l[o], c = f[fps[s]] ----------------
__global__ void __launch_bounds__(128) u_kernel()
{
    __shared__ float sWd[CC*DD];   // 32 KB, layout [d][o]
    __shared__ float st[DD];
    __shared__ float sc[CC];
    int tid = threadIdx.x;
    for (int i = tid; i < CC*DD; i += 128) sWd[i] = g_Wd[i];
    if (tid < DD) st[tid] = g_t1l[tid];
    for (int q = 0; q < 64; q++) {
        int sg = blockIdx.x * 64 + q;
        __syncthreads();
        if (tid < CC) {
            int b = sg / SS;
            int n = g_fps[sg];
            sc[tid] = g_f[((size_t)(b*NN) + n)*CC + tid];
        }
        __syncthreads();
        float a0=0.f,a1=0.f,a2=0.f,a3=0.f;
#pragma unroll
        for (int d = 0; d < CC; d += 4) {
            a0 = fmaf(sc[d+0], sWd[(d+0)*DD + tid], a0);
            a1 = fmaf(sc[d+1], sWd[(d+1)*DD + tid], a1);
            a2 = fmaf(sc[d+2], sWd[(d+2)*DD + tid], a2);
            a3 = fmaf(sc[d+3], sWd[(d+3)*DD + tid], a3);
        }
        g_u[(size_t)sg*DD + tid] = (a0+a1)+(a2+a3) + st[tid];
    }
}

// ---------------- K3: l1 (gather z + u + relu) + layer2 + k-max ----------------
__global__ void __launch_bounds__(128) l1l2_kernel(float* __restrict__ out)
{
    __shared__ float  hs[2][KK*DD];     // 32 KB
    __shared__ float  su[2*DD];
    __shared__ int    kn[2*KK];
    int tid = threadIdx.x;
    int sg0 = blockIdx.x * 2;
    int b = sg0 >> 10, s0 = sg0 & (SS-1);

    su[tid]       = g_u[(size_t)sg0*DD + tid];
    su[tid + DD]  = g_u[(size_t)sg0*DD + tid + DD];
    if (tid < 2*KK) {
        int q = tid >> 5, r = tid & 31;
        int nq = g_fps[sg0 + q];
        kn[tid] = g_knn[((size_t)(b*NN) + nq)*KK + r];
    }

    float w2[DD];
#pragma unroll
    for (int e = 0; e < DD; e++) w2[e] = g_W2s[e*DD + tid];
    float t2 = g_t2l[tid];
    __syncthreads();

    // layer-1 = gather z rows (coalesced) + u + relu; bit-identical to computing g·W1 here
#pragma unroll
    for (int q = 0; q < 2; q++) {
        float uu = su[q*DD + tid];
#pragma unroll 8
        for (int k = 0; k < KK; k++) {
            int n = kn[q*KK + k];
            float zv = g_z[((size_t)(b*NN) + n)*DD + tid];
            hs[q][k*DD + tid] = fmaxf(zv + uu, 0.f);
        }
    }
    __syncthreads();

    float m[2];
#pragma unroll
    for (int q = 0; q < 2; q++) {
        const float4* h4p = (const float4*)hs[q];
        float mm = -FLT_MAX;
        for (int k = 0; k < KK; k++) {
            float a0=0.f,a1=0.f,a2=0.f,a3=0.f;
#pragma unroll
            for (int e4 = 0; e4 < 32; e4++) {
                float4 h4 = h4p[k*32 + e4];
                a0 = fmaf(h4.x, w2[e4*4+0], a0);
                a1 = fmaf(h4.y, w2[e4*4+1], a1);
                a2 = fmaf(h4.z, w2[e4*4+2], a2);
                a3 = fmaf(h4.w, w2[e4*4+3], a3);
            }
            float acc = (a0+a1)+(a2+a3);
            mm = fmaxf(mm, acc);
        }
        m[q] = fmaxf(mm + t2, 0.f);    // max-then-(+t2,relu): monotone, identical result
    }
    size_t off = (size_t)b*(DD*SS) + (size_t)tid*SS + s0;
    float2 v; v.x = m[0]; v.y = m[1];
    *(float2*)(out + OFF_F1 + off) = v;
    *(float2*)(out + OFF_F2 + off) = v;
}

// ---------------- launch ----------------
extern "C" void kernel_launch(void* const* d_in, const int* in_sizes, int n_in,
                              void* d_out, int out_size)
{
    const float* x   = (const float*)d_in[0];
    const float* c1w = (const float*)d_in[1];
    const float* c2w = (const float*)d_in[2];
    const float* l1w = (const float*)d_in[3];
    const float* l2w = (const float*)d_in[4];
    const float* b1g = (const float*)d_in[5],  *b1b = (const float*)d_in[6],
               * b1m = (const float*)d_in[7],  *b1v = (const float*)d_in[8];
    const float* b2g = (const float*)d_in[9],  *b2b = (const float*)d_in[10],
               * b2m = (const float*)d_in[11], *b2v = (const float*)d_in[12];
    const float* g1g = (const float*)d_in[13], *g1b = (const float*)d_in[14],
               * g1m = (const float*)d_in[15], *g1v = (const float*)d_in[16];
    const float* g2g = (const float*)d_in[17], *g2b = (const float*)d_in[18],
               * g2m = (const float*)d_in[19], *g2v = (const float*)d_in[20];
    float* out = (float*)d_out;

    prep_kernel<<<64, 256>>>(c1w, c2w, l1w, l2w,
                             b1g, b1b, b1m, b1v, b2g, b2b, b2m, b2v,
                             g1g, g1b, g1m, g1v, g2g, g2b, g2m, g2v);
    mega_kernel<<<FPS_BLKS + FEATZ_BLKS + KNN_BLKS, 512>>>(x, out);
    u_kernel<<<BB*SS/64, 128>>>();
    l1l2_kernel<<<BB*SS/2, 128>>>(out);
}

// round 13
// speedup vs baseline: 11.8744x; 11.8744x over previous
#include <cuda_runtime.h>
#include <cstdint>
#include <cfloat>

#define BB 8
#define NN 8192
#define SS 1024
#define KK 32
#define CC 64
#define DD 128
#define EPSF 1e-5f

// output layout: new_xyz (8,1024,3), feature (8,128,1024), new_xyz, feature
#define OFF_F1  24576
#define OFF_NX2 1073152
#define OFF_F2  1097728

// ---------------- scratch (device globals; no allocation) ----------------
__device__ float g_f[BB*NN*CC];                 // 16 MB: per-point features
__device__ int   g_fps[BB*SS];
__device__ int   g_knn[BB*SS*KK];
__device__ float g_u[BB*SS*DD];                 // per-query layer-1 bias term
// prepped (bn-folded) weights
__device__ float g_c1s[CC*3], g_t1[CC];
__device__ float g_c2s[CC*CC], g_t2c[CC];
__device__ float g_W1s[CC*DD];   // [d][o] = lconv1_w[o][d]      * s1l[o]
__device__ float g_Wd [CC*DD];   // [d][o] = (W[o][64+d]-W[o][d])* s1l[o]
__device__ float g_t1l[DD];
__device__ float g_W2s[DD*DD];   // [e][o] = lconv2_w[o][e] * s2l[o]
__device__ float g_t2l[DD];

// ---------------- packed f32x2 helpers (per-lane rn == scalar rn) ----------------
__device__ __forceinline__ unsigned long long pk2(float a, float b) {
    unsigned long long r; asm("mov.b64 %0, {%1,%2};" : "=l"(r) : "f"(a), "f"(b)); return r;
}
__device__ __forceinline__ void upk2(unsigned long long v, float& a, float& b) {
    asm("mov.b64 {%0,%1}, %2;" : "=f"(a), "=f"(b) : "l"(v));
}
__device__ __forceinline__ unsigned long long add2(unsigned long long a, unsigned long long b) {
    unsigned long long r; asm("add.rn.f32x2 %0, %1, %2;" : "=l"(r) : "l"(a), "l"(b)); return r;
}
__device__ __forceinline__ unsigned long long mul2(unsigned long long a, unsigned long long b) {
    unsigned long long r; asm("mul.rn.f32x2 %0, %1, %2;" : "=l"(r) : "l"(a), "l"(b)); return r;
}

// ---------------- prep: fold BN into weights ----------------
__global__ void prep_kernel(
    const float* __restrict__ c1w, const float* __restrict__ c2w,
    const float* __restrict__ l1w, const float* __restrict__ l2w,
    const float* __restrict__ b1g, const float* __restrict__ b1b, const float* __restrict__ b1m, const float* __restrict__ b1v,
    const float* __restrict__ b2g, const float* __restrict__ b2b, const float* __restrict__ b2m, const float* __restrict__ b2v,
    const float* __restrict__ g1g, const float* __restrict__ g1b, const float* __restrict__ g1m, const float* __restrict__ g1v,
    const float* __restrict__ g2g, const float* __restrict__ g2b, const float* __restrict__ g2m, const float* __restrict__ g2v)
{
    int t = blockIdx.x * blockDim.x + threadIdx.x;
    int st = gridDim.x * blockDim.x;
    for (int i = t; i < CC*3; i += st) { int e = i/3; float s = b1g[e]*rsqrtf(b1v[e]+EPSF); g_c1s[i] = c1w[i]*s; }
    for (int e = t; e < CC; e += st)  { float s = b1g[e]*rsqrtf(b1v[e]+EPSF); g_t1[e] = b1b[e]-b1m[e]*s; }
    for (int i = t; i < CC*CC; i += st){ int f = i/CC; float s = b2g[f]*rsqrtf(b2v[f]+EPSF); g_c2s[i] = c2w[i]*s; }
    for (int f = t; f < CC; f += st)  { float s = b2g[f]*rsqrtf(b2v[f]+EPSF); g_t2c[f] = b2b[f]-b2m[f]*s; }
    for (int i = t; i < CC*DD; i += st){
        int d = i / DD, o = i % DD;
        float s = g1g[o]*rsqrtf(g1v[o]+EPSF);
        g_W1s[i] = l1w[o*DD + d]*s;
        g_Wd [i] = (l1w[o*DD + CC + d] - l1w[o*DD + d])*s;
    }
    for (int o = t; o < DD; o += st) { float s = g1g[o]*rsqrtf(g1v[o]+EPSF); g_t1l[o] = g1b[o]-g1m[o]*s; }
    for (int i = t; i < DD*DD; i += st){
        int e = i / DD, o = i % DD;
        float s = g2g[o]*rsqrtf(g2v[o]+EPSF);
        g_W2s[i] = l2w[o*DD + e]*s;
    }
    for (int o = t; o < DD; o += st) { float s = g2g[o]*rsqrtf(g2v[o]+EPSF); g_t2l[o] = g2b[o]-g2m[o]*s; }
}

// ---------------- K1: fused FPS (blocks 0..7) + feat (blocks 8..71), 1024 threads ----------------
__global__ void __launch_bounds__(1024) fps_feat_kernel(const float* __restrict__ x, float* __restrict__ out)
{
    int tid = threadIdx.x;
    if (blockIdx.x < BB) {
        // ---------------- FPS path ----------------
        __shared__ unsigned int pd[2][32];   // per-warp best dist bits
        __shared__ unsigned int pi[2][32];   // per-warp best inv index
        int b = blockIdx.x;
        int lane = tid & 31, wid = tid >> 5;
        const float* xb = x + (size_t)b * NN * 3;

        float rd[8];
        unsigned long long rx2[4], ry2[4], rz2[4];
#pragma unroll
        for (int jp = 0; jp < 4; jp++) {
            int i0 = tid + (2*jp)*1024, i1 = i0 + 1024;
            float ax = xb[i0*3], ay = xb[i0*3+1], az = xb[i0*3+2];
            float bx_ = xb[i1*3], by_ = xb[i1*3+1], bz_ = xb[i1*3+2];
            rx2[jp] = pk2(ax, bx_); ry2[jp] = pk2(ay, by_); rz2[jp] = pk2(az, bz_);
            rd[2*jp] = 1e10f; rd[2*jp+1] = 1e10f;
        }
        float cx = __ldg(xb), cy = __ldg(xb+1), cz = __ldg(xb+2);
        int far = 0;

        for (int t = 0; t < SS; t++) {
            if (tid == 0) {
                g_fps[b*SS + t] = far;
                int o1 = (b*SS + t) * 3;
                out[o1] = cx; out[o1+1] = cy; out[o1+2] = cz;
                out[OFF_NX2+o1] = cx; out[OFF_NX2+o1+1] = cy; out[OFF_NX2+o1+2] = cz;
            }
            unsigned long long nx = pk2(-cx, -cx), ny = pk2(-cy, -cy), nz = pk2(-cz, -cz);
            // per lane: fadd(fadd(fmul(dx,dx),fmul(dy,dy)),fmul(dz,dz)) in rn — reference rounding
#pragma unroll
            for (int jp = 0; jp < 4; jp++) {
                unsigned long long dx = add2(rx2[jp], nx);
                unsigned long long dy = add2(ry2[jp], ny);
                unsigned long long dz = add2(rz2[jp], nz);
                unsigned long long s  = add2(add2(mul2(dx,dx), mul2(dy,dy)), mul2(dz,dz));
                float s0, s1; upk2(s, s0, s1);
                rd[2*jp]   = fminf(rd[2*jp],   s0);
                rd[2*jp+1] = fminf(rd[2*jp+1], s1);
            }
            // thread-local argmax: max value, then FIRST j (ascending j == ascending global idx)
            float m = rd[0];
#pragma unroll
            for (int j = 1; j < 8; j++) m = fmaxf(m, rd[j]);
            int j0 = 7;
#pragma unroll
            for (int j = 6; j >= 0; j--) if (rd[j] == m) j0 = j;
            unsigned int mb  = __float_as_uint(m);
            unsigned int inv = (unsigned)(NN-1 - (tid + j0*1024));
            // warp reduce via REDUX: max dist bits, then max inv among tied lanes
            unsigned int wmax = __reduce_max_sync(0xffffffffu, mb);
            unsigned int winv = __reduce_max_sync(0xffffffffu, (mb == wmax) ? inv : 0u);
            if (lane == 0) { pd[t & 1][wid] = wmax; pi[t & 1][wid] = winv; }
            __syncthreads();
            // every warp redundantly reduces the 32 partials (double buffer -> no 2nd barrier)
            unsigned int d2 = pd[t & 1][lane];
            unsigned int i2 = pi[t & 1][lane];
            unsigned int gmax = __reduce_max_sync(0xffffffffu, d2);
            unsigned int ginv = __reduce_max_sync(0xffffffffu, (d2 == gmax) ? i2 : 0u);
            far = NN-1 - (int)ginv;
            cx = __ldg(xb + far*3); cy = __ldg(xb + far*3 + 1); cz = __ldg(xb + far*3 + 2);
        }
    } else {
        // ---------------- feat path ----------------
        __shared__ float sc1[CC*3], st1[CC], st2[CC];
        __shared__ float4 sc2[CC*16];
        for (int i = tid; i < CC*3; i += 1024) sc1[i] = g_c1s[i];
        for (int i = tid; i < CC; i += 1024) { st1[i] = g_t1[i]; st2[i] = g_t2c[i]; }
        for (int i = tid; i < CC*16; i += 1024) sc2[i] = ((const float4*)g_c2s)[i];
        __syncthreads();

        int p = (blockIdx.x - BB) * 1024 + tid;           // 0..65535
        float x0 = x[p*3], x1 = x[p*3+1], x2 = x[p*3+2];
        float h[CC];
#pragma unroll
        for (int e = 0; e < CC; e++)
            h[e] = fmaxf(fmaf(x2, sc1[e*3+2], fmaf(x1, sc1[e*3+1], x0*sc1[e*3])) + st1[e], 0.f);

        float* outf = g_f + (size_t)p * CC;
        for (int o = 0; o < CC; o++) {
            float a0=0.f, a1=0.f, a2=0.f, a3=0.f;
#pragma unroll
            for (int e4 = 0; e4 < 16; e4++) {
                float4 w = sc2[o*16 + e4];
                a0 = fmaf(h[e4*4+0], w.x, a0);
                a1 = fmaf(h[e4*4+1], w.y, a1);
                a2 = fmaf(h[e4*4+2], w.z, a2);
                a3 = fmaf(h[e4*4+3], w.w, a3);
            }
            outf[o] = fmaxf((a0+a1)+(a2+a3) + st2[o], 0.f);
        }
    }
}

// ---------------- K2: KNN — warp per query, register-sorted top-32, zero local memory ----------------
// cur[lane] = u64 key (distbits<<32 | idx), sorted ascending across the warp.
// Set selected = 32 smallest (d, idx) lexicographic == old insertion-sort set == lax.top_k set.
#define KNN_WPB 8      // warps (queries) per block
#define KNN_PTILE 512  // points staged in smem per tile
__global__ void __launch_bounds__(KNN_WPB*32) knn_kernel(const float* __restrict__ x)
{
    __shared__ float px[KNN_PTILE], py[KNN_PTILE], pz[KNN_PTILE];
    int tid = threadIdx.x, lane = tid & 31, wid = tid >> 5;
    int sg = blockIdx.x * KNN_WPB + wid;       // query id 0..8191 (block spans one batch)
    int b = sg >> 10;
    const float* xb = x + (size_t)b * NN * 3;
    int nq = g_fps[sg];
    float qx = xb[nq*3], qy = xb[nq*3+1], qz = xb[nq*3+2];

    unsigned long long cur = 0xFFFFFFFFFFFFFFFFull;
    unsigned long long worst = 0xFFFFFFFFFFFFFFFFull;

    for (int base = 0; base < NN; base += KNN_PTILE) {
        __syncthreads();
        for (int i = tid; i < KNN_PTILE; i += KNN_WPB*32) {
            int n = base + i;
            px[i] = xb[n*3]; py[i] = xb[n*3+1]; pz[i] = xb[n*3+2];
        }
        __syncthreads();
#pragma unroll 4
        for (int s = 0; s < KNN_PTILE; s += 32) {
            int i = s + lane;
            float dx = qx - px[i], dy = qy - py[i], dz = qz - pz[i];
            float d = fmaf(dz, dz, fmaf(dy, dy, dx*dx));
            unsigned long long cand =
                ((unsigned long long)__float_as_uint(d) << 32) | (unsigned)(base + i);
            unsigned int ball = __ballot_sync(0xffffffffu, cand < worst);
            while (ball) {                      // warp-uniform loop (ballot is uniform)
                int src = __ffs(ball) - 1; ball &= ball - 1;
                unsigned long long ck = __shfl_sync(0xffffffffu, cand, src);
                if (ck < worst) {               // uniform (ck, worst uniform)
                    unsigned int lt = __ballot_sync(0xffffffffu, cur < ck);
                    int pos = __popc(lt);       // insertion position (keys unique: idx in key)
                    unsigned long long up = __shfl_up_sync(0xffffffffu, cur, 1);
                    if (lane > pos) cur = up;   // shift tail; lane 31's (old worst) evicted
                    if (lane == pos) cur = ck;
                    worst = __shfl_sync(0xffffffffu, cur, 31);
                }
            }
        }
    }
    // order within the 32 irrelevant downstream (max over k)
    g_knn[(size_t)sg*KK + lane] = (int)(unsigned)(cur & 0xffffffffu);
}

// ---------------- K3: u[s][o] = c·(Wb-Wa)'[o] + t1l[o], c = f[fps[s]] ----------------
__global__ void __launch_bounds__(128) u_kernel()
{
    __shared__ float sWd[CC*DD];   // 32 KB, layout [d][o]
    __shared__ float st[DD];
    __shared__ float sc[CC];
    int tid = threadIdx.x;
    for (int i = tid; i < CC*DD; i += 128) sWd[i] = g_Wd[i];
    if (tid < DD) st[tid] = g_t1l[tid];
    for (int q = 0; q < 64; q++) {
        int sg = blockIdx.x * 64 + q;
        __syncthreads();
        if (tid < CC) {
            int b = sg / SS;
            int n = g_fps[sg];
            sc[tid] = g_f[((size_t)(b*NN) + n)*CC + tid];
        }
        __syncthreads();
        float a0=0.f,a1=0.f,a2=0.f,a3=0.f;
#pragma unroll
        for (int d = 0; d < CC; d += 4) {
            a0 = fmaf(sc[d+0], sWd[(d+0)*DD + tid], a0);
            a1 = fmaf(sc[d+1], sWd[(d+1)*DD + tid], a1);
            a2 = fmaf(sc[d+2], sWd[(d+2)*DD + tid], a2);
            a3 = fmaf(sc[d+3], sWd[(d+3)*DD + tid], a3);
        }
        g_u[(size_t)sg*DD + tid] = (a0+a1)+(a2+a3) + st[tid];
    }
}

// ---------------- K4: fused layer1 + layer2 + k-max (R10/R8 scalar version) ----------------
__global__ void __launch_bounds__(128) l1l2_kernel(float* __restrict__ out)
{
    __shared__ float4 gs[KK*16];        // 8 KB: grouped rows of one query
    __shared__ float  hs[2][KK*DD];     // 32 KB: layer-1 activations, 2 queries
    __shared__ float  su[2*DD];
    __shared__ int    kn[2*KK];
    int tid = threadIdx.x;
    int sg0 = blockIdx.x * 2;
    int b = sg0 >> 10, s0 = sg0 & (SS-1);

    su[tid]       = g_u[(size_t)sg0*DD + tid];
    su[tid + DD]  = g_u[(size_t)sg0*DD + tid + DD];
    if (tid < 2*KK) kn[tid] = g_knn[(size_t)sg0*KK + tid];

    float w1[CC];
#pragma unroll
    for (int d = 0; d < CC; d++) w1[d] = g_W1s[d*DD + tid];

    for (int q = 0; q < 2; q++) {
        __syncthreads();
#pragma unroll
        for (int j = 0; j < 4; j++) {
            int idx = tid + j*128;
            int r = idx >> 4, c = idx & 15;
            int n = kn[q*KK + r];
            gs[idx] = ((const float4*)(g_f + ((size_t)(b*NN) + n)*CC))[c];
        }
        __syncthreads();
        float uu = su[q*DD + tid];
        for (int k = 0; k < KK; k++) {
            float a0=0.f,a1=0.f,a2=0.f,a3=0.f;
#pragma unroll
            for (int d4 = 0; d4 < 16; d4++) {
                float4 g4 = gs[k*16 + d4];
                a0 = fmaf(g4.x, w1[d4*4+0], a0);
                a1 = fmaf(g4.y, w1[d4*4+1], a1);
                a2 = fmaf(g4.z, w1[d4*4+2], a2);
                a3 = fmaf(g4.w, w1[d4*4+3], a3);
            }
            hs[q][k*DD + tid] = fmaxf((a0+a1)+(a2+a3) + uu, 0.f);
        }
    }

    float w2[DD];
#pragma unroll
    for (int e = 0; e < DD; e++) w2[e] = g_W2s[e*DD + tid];
    float t2 = g_t2l[tid];
    __syncthreads();

    float m[2];
#pragma unroll
    for (int q = 0; q < 2; q++) {
        const float4* h4p = (const float4*)hs[q];
        float mm = -FLT_MAX;
        for (int k = 0; k < KK; k++) {
            float a0=0.f,a1=0.f,a2=0.f,a3=0.f;
#pragma unroll
            for (int e4 = 0; e4 < 32; e4++) {
                float4 h4 = h4p[k*32 + e4];
                a0 = fmaf(h4.x, w2[e4*4+0], a0);
                a1 = fmaf(h4.y, w2[e4*4+1], a1);
                a2 = fmaf(h4.z, w2[e4*4+2], a2);
                a3 = fmaf(h4.w, w2[e4*4+3], a3);
            }
            float acc = (a0+a1)+(a2+a3);
            mm = fmaxf(mm, acc);
        }
        m[q] = fmaxf(mm + t2, 0.f);    // max-then-(+t2,relu): monotone, identical result
    }
    size_t off = (size_t)b*(DD*SS) + (size_t)tid*SS + s0;
    float2 v; v.x = m[0]; v.y = m[1];
    *(float2*)(out + OFF_F1 + off) = v;
    *(float2*)(out + OFF_F2 + off) = v;
}

// ---------------- launch ----------------
extern "C" void kernel_launch(void* const* d_in, const int* in_sizes, int n_in,
                              void* d_out, int out_size)
{
    const float* x   = (const float*)d_in[0];
    const float* c1w = (const float*)d_in[1];
    const float* c2w = (const float*)d_in[2];
    const float* l1w = (const float*)d_in[3];
    const float* l2w = (const float*)d_in[4];
    const float* b1g = (const float*)d_in[5],  *b1b = (const float*)d_in[6],
               * b1m = (const float*)d_in[7],  *b1v = (const float*)d_in[8];
    const float* b2g = (const float*)d_in[9],  *b2b = (const float*)d_in[10],
               * b2m = (const float*)d_in[11], *b2v = (const float*)d_in[12];
    const float* g1g = (const float*)d_in[13], *g1b = (const float*)d_in[14],
               * g1m = (const float*)d_in[15], *g1v = (const float*)d_in[16];
    const float* g2g = (const float*)d_in[17], *g2b = (const float*)d_in[18],
               * g2m = (const float*)d_in[19], *g2v = (const float*)d_in[20];
    float* out = (float*)d_out;

    prep_kernel<<<64, 256>>>(c1w, c2w, l1w, l2w,
                             b1g, b1b, b1m, b1v, b2g, b2b, b2m, b2v,
                             g1g, g1b, g1m, g1v, g2g, g2b, g2m, g2v);
    fps_feat_kernel<<<BB + BB*NN/1024, 1024>>>(x, out);   // 8 fps blocks + 64 feat blocks
    knn_kernel<<<BB*SS/KNN_WPB, KNN_WPB*32>>>(x);         // 1024 blocks, warp per query
    u_kernel<<<BB*SS/64, 128>>>();
    l1l2_kernel<<<BB*SS/2, 128>>>(out);
}